// round 1
// baseline (speedup 1.0000x reference)
#include <cuda_runtime.h>

#define NI 256
#define QKD 32
#define BSZ 4
#define HW 4096   // 64*64
#define QT 64
#define KT 64

// Scratch: Q [b][n][32], K [b][n][32], V [b][n][256]
__device__ float g_q[BSZ * HW * QKD];
__device__ float g_k[BSZ * HW * QKD];
__device__ float g_v[BSZ * HW * NI];

// ---------------------------------------------------------------------------
// Projection kernel: per block, 32 tokens x 320 output channels (32 q, 32 k, 256 v)
// x tile staged in SMEM as [c][token]; outputs staged in SMEM then written
// coalesced to token-major scratch buffers.
// ---------------------------------------------------------------------------
__global__ __launch_bounds__(256, 2)
void proj_kernel(const float* __restrict__ x,
                 const float* __restrict__ wq, const float* __restrict__ bq,
                 const float* __restrict__ wk, const float* __restrict__ bk,
                 const float* __restrict__ wv, const float* __restrict__ bv)
{
    extern __shared__ float smem[];
    float* xs = smem;              // [256][32]
    float* ys = smem + 256 * 32;   // [320][36]  (36: 16B-aligned rows, bank-spread)

    const int tid = threadIdx.x;
    const int blk = blockIdx.x;
    const int b  = blk >> 7;           // 128 tiles of 32 tokens per batch
    const int n0 = (blk & 127) * 32;
    const float* xb = x + (size_t)b * NI * HW;

    // load x tile (coalesced): xs[c][t]
    for (int idx = tid; idx < 256 * 32; idx += 256) {
        int c = idx >> 5, t = idx & 31;
        xs[idx] = xb[(size_t)c * HW + n0 + t];
    }
    __syncthreads();

    const int oslot = tid >> 3;   // 0..31
    const int tq    = tid & 7;    // token quad (4 tokens)
    const float4* xs4 = (const float4*)xs;

    for (int i = 0; i < 10; i++) {
        int o = oslot + 32 * i;   // 0..319
        const float* wrow; float bias;
        if (o < 32)       { wrow = wq + o * NI;        bias = bq[o]; }
        else if (o < 64)  { wrow = wk + (o - 32) * NI; bias = bk[o - 32]; }
        else              { wrow = wv + (o - 64) * NI; bias = bv[o - 64]; }
        float a0 = bias, a1 = bias, a2 = bias, a3 = bias;
        #pragma unroll 8
        for (int c = 0; c < NI; c++) {
            float w = __ldg(wrow + c);
            float4 xv = xs4[c * 8 + tq];
            a0 += w * xv.x; a1 += w * xv.y; a2 += w * xv.z; a3 += w * xv.w;
        }
        float4* yrow = (float4*)(ys + o * 36);
        yrow[tq] = make_float4(a0, a1, a2, a3);
    }
    __syncthreads();

    // coalesced global writes
    float* gq = g_q + ((size_t)b * HW + n0) * QKD;
    float* gk = g_k + ((size_t)b * HW + n0) * QKD;
    float* gv = g_v + ((size_t)b * HW + n0) * NI;
    for (int idx = tid; idx < 32 * QKD; idx += 256) {
        int n = idx >> 5, o = idx & 31;
        gq[idx] = ys[o * 36 + n];
        gk[idx] = ys[(32 + o) * 36 + n];
    }
    for (int idx = tid; idx < 32 * NI; idx += 256) {
        int n = idx >> 8, c = idx & 255;
        gv[idx] = ys[(64 + c) * 36 + n];
    }
}

// ---------------------------------------------------------------------------
// Flash-attention kernel: block = 64 queries, 256 threads.
// thread -> (r = tid/4, j = tid&3); thread j owns float4 column groups g ≡ j mod 4
// (bank-conflict-free LDS.128 in the PV mainloop).
// Epilogue fuses out = gamma*O/l + x.
// ---------------------------------------------------------------------------
__global__ __launch_bounds__(256, 2)
void attn_kernel(const float* __restrict__ x, const float* __restrict__ gamma,
                 float* __restrict__ out)
{
    extern __shared__ float smem[];
    float* Qs  = smem;                 // [64][33]  (pad 33 -> row-broadcast conflict-free)
    float* Kst = Qs + 64 * 33;         // [32][68]  K transposed: [d][m], pad 68
    float* Ss  = Kst + 32 * 68;        // [64][68]  P tile
    float* Vs  = Ss + 64 * 68;         // [64][256]

    const int tid = threadIdx.x;
    const int b  = blockIdx.y;
    const int n0 = blockIdx.x * QT;
    const int r = tid >> 2;
    const int j = tid & 3;

    const float* Qg = g_q + ((size_t)b * HW + n0) * QKD;
    for (int idx = tid; idx < QT * QKD; idx += 256) {
        int n = idx >> 5, d = idx & 31;
        Qs[n * 33 + d] = Qg[idx];
    }

    float acc[64];
    #pragma unroll
    for (int i = 0; i < 64; i++) acc[i] = 0.f;
    float mrun = -1e30f, lrun = 0.f;
    __syncthreads();

    for (int kt = 0; kt < HW / KT; kt++) {
        const int k0 = kt * KT;
        // load K tile transposed [d][m] and V tile [m][c]
        const float* Kg = g_k + ((size_t)b * HW + k0) * QKD;
        for (int idx = tid; idx < KT * QKD; idx += 256) {
            int m = idx >> 5, d = idx & 31;
            Kst[d * 68 + m] = Kg[idx];
        }
        const float4* Vg = (const float4*)(g_v + ((size_t)b * HW + k0) * NI);
        float4* Vs4 = (float4*)Vs;
        for (int idx = tid; idx < KT * NI / 4; idx += 256)
            Vs4[idx] = Vg[idx];
        __syncthreads();

        // S = Q K^T for this thread's 16 m's (float4 m-groups g = j + 4*mm)
        float s[16];
        #pragma unroll
        for (int i = 0; i < 16; i++) s[i] = 0.f;
        #pragma unroll 4
        for (int d = 0; d < QKD; d++) {
            float q = Qs[r * 33 + d];
            const float4* kr = (const float4*)(Kst + d * 68);
            #pragma unroll
            for (int mm = 0; mm < 4; mm++) {
                float4 k4 = kr[j + 4 * mm];
                s[mm * 4 + 0] += q * k4.x;
                s[mm * 4 + 1] += q * k4.y;
                s[mm * 4 + 2] += q * k4.z;
                s[mm * 4 + 3] += q * k4.w;
            }
        }

        // online softmax (row stats shared across the 4 j-threads via shfl)
        float mloc = s[0];
        #pragma unroll
        for (int i = 1; i < 16; i++) mloc = fmaxf(mloc, s[i]);
        mloc = fmaxf(mloc, __shfl_xor_sync(0xffffffffu, mloc, 1));
        mloc = fmaxf(mloc, __shfl_xor_sync(0xffffffffu, mloc, 2));
        float mnew  = fmaxf(mrun, mloc);
        float alpha = __expf(mrun - mnew);
        float ls = 0.f;
        #pragma unroll
        for (int i = 0; i < 16; i++) {
            float p = __expf(s[i] - mnew);
            s[i] = p; ls += p;
        }
        ls += __shfl_xor_sync(0xffffffffu, ls, 1);
        ls += __shfl_xor_sync(0xffffffffu, ls, 2);
        lrun = lrun * alpha + ls;
        mrun = mnew;
        #pragma unroll
        for (int i = 0; i < 64; i++) acc[i] *= alpha;

        // publish P row-chunk
        float4* srow = (float4*)(Ss + r * 68);
        #pragma unroll
        for (int mm = 0; mm < 4; mm++)
            srow[j + 4 * mm] = make_float4(s[mm*4], s[mm*4+1], s[mm*4+2], s[mm*4+3]);
        __syncthreads();

        // O += P V  (dominant loop; LDS.128 conflict-free via j-interleave)
        #pragma unroll 2
        for (int m = 0; m < KT; m++) {
            float p = Ss[r * 68 + m];
            const float4* vr = (const float4*)(Vs + m * NI);
            #pragma unroll
            for (int cc = 0; cc < 16; cc++) {
                float4 v4 = vr[j + 4 * cc];
                acc[cc * 4 + 0] += p * v4.x;
                acc[cc * 4 + 1] += p * v4.y;
                acc[cc * 4 + 2] += p * v4.z;
                acc[cc * 4 + 3] += p * v4.w;
            }
        }
        __syncthreads();
    }

    // epilogue: out[b][c][n] = gamma[c] * O[n][c] / l + x[b][c][n]
    const float rinv = 1.f / lrun;
    const int n = n0 + r;
    const float* xb = x   + (size_t)b * NI * HW;
    float*       ob = out + (size_t)b * NI * HW;
    #pragma unroll
    for (int cc = 0; cc < 16; cc++) {
        #pragma unroll
        for (int e = 0; e < 4; e++) {
            int c = 4 * (j + 4 * cc) + e;
            size_t gi = (size_t)c * HW + n;
            ob[gi] = gamma[c] * (acc[cc * 4 + e] * rinv) + xb[gi];
        }
    }
}

extern "C" void kernel_launch(void* const* d_in, const int* in_sizes, int n_in,
                              void* d_out, int out_size)
{
    const float* x     = (const float*)d_in[0];
    const float* wq    = (const float*)d_in[1];
    const float* bq    = (const float*)d_in[2];
    const float* wk    = (const float*)d_in[3];
    const float* bk    = (const float*)d_in[4];
    const float* wv    = (const float*)d_in[5];
    const float* bv    = (const float*)d_in[6];
    const float* gamma = (const float*)d_in[7];
    float* out = (float*)d_out;

    const int smem_proj = (256 * 32 + 320 * 36) * 4;                  // ~78.8 KB
    const int smem_attn = (64 * 33 + 32 * 68 + 64 * 68 + 64 * 256) * 4; // ~97.8 KB
    cudaFuncSetAttribute(proj_kernel, cudaFuncAttributeMaxDynamicSharedMemorySize, smem_proj);
    cudaFuncSetAttribute(attn_kernel, cudaFuncAttributeMaxDynamicSharedMemorySize, smem_attn);

    proj_kernel<<<512, 256, smem_proj>>>(x, wq, bq, wk, bk, wv, bv);
    attn_kernel<<<dim3(HW / QT, BSZ), 256, smem_attn>>>(x, gamma, out);
}

// round 2
// speedup vs baseline: 2.1490x; 2.1490x over previous
#include <cuda_runtime.h>

#define NI 256
#define QKD 32
#define BSZ 4
#define HW 4096   // 64*64
#define QT 64
#define KT 64

typedef unsigned long long ull;

// Scratch: Q [b][n][32], K [b][n][32], V [b][n][256]
__device__ float g_q[BSZ * HW * QKD];
__device__ float g_k[BSZ * HW * QKD];
__device__ float g_v[BSZ * HW * NI];

// ---- packed f32x2 helpers (Blackwell fma.rn.f32x2, rt=1/SMSP) -------------
__device__ __forceinline__ ull pack2(float x, float y) {
    ull r; asm("mov.b64 %0, {%1, %2};" : "=l"(r) : "f"(x), "f"(y)); return r;
}
__device__ __forceinline__ void unpack2(ull v, float& x, float& y) {
    asm("mov.b64 {%0, %1}, %2;" : "=f"(x), "=f"(y) : "l"(v));
}
__device__ __forceinline__ ull ffma2(ull a, ull b, ull c) {
    ull d; asm("fma.rn.f32x2 %0, %1, %2, %3;" : "=l"(d) : "l"(a), "l"(b), "l"(c));
    return d;
}
__device__ __forceinline__ ull fmul2(ull a, ull b) {
    ull d; asm("mul.rn.f32x2 %0, %1, %2;" : "=l"(d) : "l"(a), "l"(b));
    return d;
}

// ---------------------------------------------------------------------------
// Projection kernel: per block, 32 tokens x 320 output channels.
// ---------------------------------------------------------------------------
__global__ __launch_bounds__(256, 2)
void proj_kernel(const float* __restrict__ x,
                 const float* __restrict__ wq, const float* __restrict__ bq,
                 const float* __restrict__ wk, const float* __restrict__ bk,
                 const float* __restrict__ wv, const float* __restrict__ bv)
{
    extern __shared__ float smem[];
    float* xs = smem;              // [256][32]
    float* ys = smem + 256 * 32;   // [320][36]

    const int tid = threadIdx.x;
    const int blk = blockIdx.x;
    const int b  = blk >> 7;
    const int n0 = (blk & 127) * 32;
    const float* xb = x + (size_t)b * NI * HW;

    for (int idx = tid; idx < 256 * 32; idx += 256) {
        int c = idx >> 5, t = idx & 31;
        xs[idx] = xb[(size_t)c * HW + n0 + t];
    }
    __syncthreads();

    const int oslot = tid >> 3;
    const int tq    = tid & 7;
    const ulonglong2* xs2 = (const ulonglong2*)xs;

    for (int i = 0; i < 10; i++) {
        int o = oslot + 32 * i;
        const float* wrow; float bias;
        if (o < 32)       { wrow = wq + o * NI;        bias = bq[o]; }
        else if (o < 64)  { wrow = wk + (o - 32) * NI; bias = bk[o - 32]; }
        else              { wrow = wv + (o - 64) * NI; bias = bv[o - 64]; }
        ull a01 = pack2(bias, bias), a23 = a01;
        #pragma unroll 8
        for (int c = 0; c < NI; c++) {
            float w = __ldg(wrow + c);
            ull wp = pack2(w, w);
            ulonglong2 xv = xs2[c * 8 + tq];
            a01 = ffma2(wp, xv.x, a01);
            a23 = ffma2(wp, xv.y, a23);
        }
        float4 r;
        unpack2(a01, r.x, r.y);
        unpack2(a23, r.z, r.w);
        ((float4*)(ys + o * 36))[tq] = r;
    }
    __syncthreads();

    float* gq = g_q + ((size_t)b * HW + n0) * QKD;
    float* gk = g_k + ((size_t)b * HW + n0) * QKD;
    float* gv = g_v + ((size_t)b * HW + n0) * NI;
    for (int idx = tid; idx < 32 * QKD; idx += 256) {
        int n = idx >> 5, o = idx & 31;
        gq[idx] = ys[o * 36 + n];
        gk[idx] = ys[(32 + o) * 36 + n];
    }
    for (int idx = tid; idx < 32 * NI; idx += 256) {
        int n = idx >> 8, c = idx & 255;
        gv[idx] = ys[(64 + c) * 36 + n];
    }
}

// ---------------------------------------------------------------------------
// Flash-attention: 64 queries/block, 256 threads.
// Thread (ty = tid>>4, tx = tid&15): 4 rows (4*ty..) x 16 cols (groups tx+16*cc).
// All mainloop math in fma.rn.f32x2. P and Q staged TRANSPOSED in SMEM so the
// per-iteration row loads are single LDS.128s.
// ---------------------------------------------------------------------------
__global__ __launch_bounds__(256, 2)
void attn_kernel(const float* __restrict__ x, const float* __restrict__ gamma,
                 float* __restrict__ out)
{
    extern __shared__ float smem[];
    float* Qt  = smem;                 // [32][68]  Q^T : [d][r]
    float* Kst = Qt + 32 * 68;         // [32][68]  K^T : [d][m]
    float* Sst = Kst + 32 * 68;        // [64][68]  P^T : [m][r]
    float* Vs  = Sst + 64 * 68;        // [64][256] V   : [m][c]
    float* Ot  = smem;                 // reuse for epilogue: [256][68] (fits)

    const int tid = threadIdx.x;
    const int b  = blockIdx.y;
    const int n0 = blockIdx.x * QT;
    const int ty = tid >> 4;           // 0..15 -> rows 4*ty..4*ty+3
    const int tx = tid & 15;           // 0..15 -> col groups tx+16*cc, m-group tx

    // load Q transposed
    const float* Qg = g_q + ((size_t)b * HW + n0) * QKD;
    for (int idx = tid; idx < QT * QKD; idx += 256) {
        int r = idx >> 5, d = idx & 31;
        Qt[d * 68 + r] = Qg[idx];
    }

    ull acc[32];                       // [rr][8] : 4 rows x 16 cols packed
    #pragma unroll
    for (int i = 0; i < 32; i++) acc[i] = 0ull;
    float mrun[4] = {-1e30f, -1e30f, -1e30f, -1e30f};
    float lrun[4] = {0.f, 0.f, 0.f, 0.f};
    __syncthreads();

    for (int kt = 0; kt < HW / KT; kt++) {
        const int k0 = kt * KT;
        const float* Kg = g_k + ((size_t)b * HW + k0) * QKD;
        for (int idx = tid; idx < KT * QKD; idx += 256) {
            int m = idx >> 5, d = idx & 31;
            Kst[d * 68 + m] = Kg[idx];
        }
        const float4* Vg = (const float4*)(g_v + ((size_t)b * HW + k0) * NI);
        float4* Vs4 = (float4*)Vs;
        for (int idx = tid; idx < KT * NI / 4; idx += 256)
            Vs4[idx] = Vg[idx];
        __syncthreads();

        // ---- S = Q K^T : 4 rows x 4 m per thread, packed over m pairs ----
        ull s01[4], s23[4];
        #pragma unroll
        for (int rr = 0; rr < 4; rr++) { s01[rr] = 0ull; s23[rr] = 0ull; }
        #pragma unroll 4
        for (int d = 0; d < QKD; d++) {
            float4 q4 = *(const float4*)(Qt + d * 68 + 4 * ty);
            ulonglong2 k2 = *(const ulonglong2*)(Kst + d * 68 + 4 * tx);
            ull q0 = pack2(q4.x, q4.x), q1 = pack2(q4.y, q4.y);
            ull q2 = pack2(q4.z, q4.z), q3 = pack2(q4.w, q4.w);
            s01[0] = ffma2(q0, k2.x, s01[0]); s23[0] = ffma2(q0, k2.y, s23[0]);
            s01[1] = ffma2(q1, k2.x, s01[1]); s23[1] = ffma2(q1, k2.y, s23[1]);
            s01[2] = ffma2(q2, k2.x, s01[2]); s23[2] = ffma2(q2, k2.y, s23[2]);
            s01[3] = ffma2(q3, k2.x, s01[3]); s23[3] = ffma2(q3, k2.y, s23[3]);
        }

        // ---- online softmax (row stats across the 16 tx lanes) ----
        float px[4][4];
        #pragma unroll
        for (int rr = 0; rr < 4; rr++) {
            float sx0, sx1, sx2, sx3;
            unpack2(s01[rr], sx0, sx1);
            unpack2(s23[rr], sx2, sx3);
            float mloc = fmaxf(fmaxf(sx0, sx1), fmaxf(sx2, sx3));
            mloc = fmaxf(mloc, __shfl_xor_sync(0xffffffffu, mloc, 1));
            mloc = fmaxf(mloc, __shfl_xor_sync(0xffffffffu, mloc, 2));
            mloc = fmaxf(mloc, __shfl_xor_sync(0xffffffffu, mloc, 4));
            mloc = fmaxf(mloc, __shfl_xor_sync(0xffffffffu, mloc, 8));
            float mnew  = fmaxf(mrun[rr], mloc);
            float alpha = __expf(mrun[rr] - mnew);
            float p0 = __expf(sx0 - mnew), p1 = __expf(sx1 - mnew);
            float p2 = __expf(sx2 - mnew), p3 = __expf(sx3 - mnew);
            px[rr][0] = p0; px[rr][1] = p1; px[rr][2] = p2; px[rr][3] = p3;
            float ls = p0 + p1 + p2 + p3;
            ls += __shfl_xor_sync(0xffffffffu, ls, 1);
            ls += __shfl_xor_sync(0xffffffffu, ls, 2);
            ls += __shfl_xor_sync(0xffffffffu, ls, 4);
            ls += __shfl_xor_sync(0xffffffffu, ls, 8);
            lrun[rr] = lrun[rr] * alpha + ls;
            mrun[rr] = mnew;
            ull ap = pack2(alpha, alpha);
            #pragma unroll
            for (int i = 0; i < 8; i++) acc[rr * 8 + i] = fmul2(acc[rr * 8 + i], ap);
        }
        // publish P transposed: Sst[m][r]
        #pragma unroll
        for (int mm = 0; mm < 4; mm++) {
            float4 v = make_float4(px[0][mm], px[1][mm], px[2][mm], px[3][mm]);
            *(float4*)(Sst + (4 * tx + mm) * 68 + 4 * ty) = v;
        }
        __syncthreads();

        // ---- O += P V : 1 LDS.128 (p) + 4 LDS.128 (V) + 32 FMA2 per m ----
        #pragma unroll 2
        for (int m = 0; m < KT; m++) {
            float4 pv = *(const float4*)(Sst + m * 68 + 4 * ty);
            ull p0 = pack2(pv.x, pv.x), p1 = pack2(pv.y, pv.y);
            ull p2 = pack2(pv.z, pv.z), p3 = pack2(pv.w, pv.w);
            const ulonglong2* vr = (const ulonglong2*)(Vs + m * NI);
            #pragma unroll
            for (int cc = 0; cc < 4; cc++) {
                ulonglong2 v2 = vr[tx + 16 * cc];
                acc[0 * 8 + 2 * cc]     = ffma2(p0, v2.x, acc[0 * 8 + 2 * cc]);
                acc[0 * 8 + 2 * cc + 1] = ffma2(p0, v2.y, acc[0 * 8 + 2 * cc + 1]);
                acc[1 * 8 + 2 * cc]     = ffma2(p1, v2.x, acc[1 * 8 + 2 * cc]);
                acc[1 * 8 + 2 * cc + 1] = ffma2(p1, v2.y, acc[1 * 8 + 2 * cc + 1]);
                acc[2 * 8 + 2 * cc]     = ffma2(p2, v2.x, acc[2 * 8 + 2 * cc]);
                acc[2 * 8 + 2 * cc + 1] = ffma2(p2, v2.y, acc[2 * 8 + 2 * cc + 1]);
                acc[3 * 8 + 2 * cc]     = ffma2(p3, v2.x, acc[3 * 8 + 2 * cc]);
                acc[3 * 8 + 2 * cc + 1] = ffma2(p3, v2.y, acc[3 * 8 + 2 * cc + 1]);
            }
        }
        __syncthreads();
    }

    // ---- epilogue: normalize, transpose via SMEM, coalesced gamma*O + x ----
    float rinv[4];
    #pragma unroll
    for (int rr = 0; rr < 4; rr++) rinv[rr] = 1.f / lrun[rr];

    #pragma unroll
    for (int rr = 0; rr < 4; rr++) {
        #pragma unroll
        for (int cc = 0; cc < 4; cc++) {
            #pragma unroll
            for (int h = 0; h < 2; h++) {
                float o0, o1;
                unpack2(acc[rr * 8 + 2 * cc + h], o0, o1);
                int c0 = 4 * (tx + 16 * cc) + 2 * h;
                Ot[(size_t)c0 * 68 + 4 * ty + rr]       = o0 * rinv[rr];
                Ot[(size_t)(c0 + 1) * 68 + 4 * ty + rr] = o1 * rinv[rr];
            }
        }
    }
    __syncthreads();

    const float* xb = x   + (size_t)b * NI * HW;
    float*       ob = out + (size_t)b * NI * HW;
    #pragma unroll 4
    for (int pass = 0; pass < 16; pass++) {
        int c = pass * 16 + ty;
        float ga = gamma[c];
        float4 o = *(const float4*)(Ot + c * 68 + 4 * tx);
        size_t gi = (size_t)c * HW + n0 + 4 * tx;
        float4 xv = *(const float4*)(xb + gi);
        *(float4*)(ob + gi) = make_float4(ga * o.x + xv.x, ga * o.y + xv.y,
                                          ga * o.z + xv.z, ga * o.w + xv.w);
    }
}

extern "C" void kernel_launch(void* const* d_in, const int* in_sizes, int n_in,
                              void* d_out, int out_size)
{
    const float* x     = (const float*)d_in[0];
    const float* wq    = (const float*)d_in[1];
    const float* bq    = (const float*)d_in[2];
    const float* wk    = (const float*)d_in[3];
    const float* bk    = (const float*)d_in[4];
    const float* wv    = (const float*)d_in[5];
    const float* bv    = (const float*)d_in[6];
    const float* gamma = (const float*)d_in[7];
    float* out = (float*)d_out;

    const int smem_proj = (256 * 32 + 320 * 36) * 4;
    const int smem_attn = (32 * 68 + 32 * 68 + 64 * 68 + 64 * 256) * 4; // 91.6 KB
    cudaFuncSetAttribute(proj_kernel, cudaFuncAttributeMaxDynamicSharedMemorySize, smem_proj);
    cudaFuncSetAttribute(attn_kernel, cudaFuncAttributeMaxDynamicSharedMemorySize, smem_attn);

    proj_kernel<<<512, 256, smem_proj>>>(x, wq, bq, wk, bk, wv, bv);
    attn_kernel<<<dim3(HW / QT, BSZ), 256, smem_attn>>>(x, gamma, out);
}

// round 3
// speedup vs baseline: 2.1495x; 1.0002x over previous
#include <cuda_runtime.h>

#define NI 256
#define QKD 32
#define BSZ 4
#define HW 4096   // 64*64
#define QT 64
#define KT 64

typedef unsigned long long ull;

// Scratch: Q [b][n][32], K [b][n][32], V [b][n][256]
__device__ float g_q[BSZ * HW * QKD];
__device__ float g_k[BSZ * HW * QKD];
__device__ float g_v[BSZ * HW * NI];

// ---- packed f32x2 helpers (Blackwell fma.rn.f32x2, rt=1/SMSP) -------------
__device__ __forceinline__ ull pack2(float x, float y) {
    ull r; asm("mov.b64 %0, {%1, %2};" : "=l"(r) : "f"(x), "f"(y)); return r;
}
__device__ __forceinline__ void unpack2(ull v, float& x, float& y) {
    asm("mov.b64 {%0, %1}, %2;" : "=f"(x), "=f"(y) : "l"(v));
}
__device__ __forceinline__ ull ffma2(ull a, ull b, ull c) {
    ull d; asm("fma.rn.f32x2 %0, %1, %2, %3;" : "=l"(d) : "l"(a), "l"(b), "l"(c));
    return d;
}
__device__ __forceinline__ ull fmul2(ull a, ull b) {
    ull d; asm("mul.rn.f32x2 %0, %1, %2;" : "=l"(d) : "l"(a), "l"(b));
    return d;
}

// ---------------------------------------------------------------------------
// Projection kernel: per block, 32 tokens x 320 output channels.
// ---------------------------------------------------------------------------
__global__ __launch_bounds__(256, 2)
void proj_kernel(const float* __restrict__ x,
                 const float* __restrict__ wq, const float* __restrict__ bq,
                 const float* __restrict__ wk, const float* __restrict__ bk,
                 const float* __restrict__ wv, const float* __restrict__ bv)
{
    extern __shared__ float smem[];
    float* xs = smem;              // [256][32]
    float* ys = smem + 256 * 32;   // [320][36]

    const int tid = threadIdx.x;
    const int blk = blockIdx.x;
    const int b  = blk >> 7;
    const int n0 = (blk & 127) * 32;
    const float* xb = x + (size_t)b * NI * HW;

    for (int idx = tid; idx < 256 * 32; idx += 256) {
        int c = idx >> 5, t = idx & 31;
        xs[idx] = xb[(size_t)c * HW + n0 + t];
    }
    __syncthreads();

    const int oslot = tid >> 3;
    const int tq    = tid & 7;
    const ulonglong2* xs2 = (const ulonglong2*)xs;

    for (int i = 0; i < 10; i++) {
        int o = oslot + 32 * i;
        const float* wrow; float bias;
        if (o < 32)       { wrow = wq + o * NI;        bias = bq[o]; }
        else if (o < 64)  { wrow = wk + (o - 32) * NI; bias = bk[o - 32]; }
        else              { wrow = wv + (o - 64) * NI; bias = bv[o - 64]; }
        ull a01 = pack2(bias, bias), a23 = a01;
        #pragma unroll 8
        for (int c = 0; c < NI; c++) {
            float w = __ldg(wrow + c);
            ull wp = pack2(w, w);
            ulonglong2 xv = xs2[c * 8 + tq];
            a01 = ffma2(wp, xv.x, a01);
            a23 = ffma2(wp, xv.y, a23);
        }
        float4 r;
        unpack2(a01, r.x, r.y);
        unpack2(a23, r.z, r.w);
        ((float4*)(ys + o * 36))[tq] = r;
    }
    __syncthreads();

    float* gq = g_q + ((size_t)b * HW + n0) * QKD;
    float* gk = g_k + ((size_t)b * HW + n0) * QKD;
    float* gv = g_v + ((size_t)b * HW + n0) * NI;
    for (int idx = tid; idx < 32 * QKD; idx += 256) {
        int n = idx >> 5, o = idx & 31;
        gq[idx] = ys[o * 36 + n];
        gk[idx] = ys[(32 + o) * 36 + n];
    }
    for (int idx = tid; idx < 32 * NI; idx += 256) {
        int n = idx >> 8, c = idx & 255;
        gv[idx] = ys[(64 + c) * 36 + n];
    }
}

// ---------------------------------------------------------------------------
// Flash-attention: 64 queries/block, 256 threads.
// Thread (ty = tid>>4, tx = tid&15): 4 rows (4*ty..) x 16 cols (groups tx+16*cc).
// All mainloop math in fma.rn.f32x2. P and Q staged TRANSPOSED in SMEM so the
// per-iteration row loads are single LDS.128s.
// ---------------------------------------------------------------------------
__global__ __launch_bounds__(256, 2)
void attn_kernel(const float* __restrict__ x, const float* __restrict__ gamma,
                 float* __restrict__ out)
{
    extern __shared__ float smem[];
    float* Qt  = smem;                 // [32][68]  Q^T : [d][r]
    float* Kst = Qt + 32 * 68;         // [32][68]  K^T : [d][m]
    float* Sst = Kst + 32 * 68;        // [64][68]  P^T : [m][r]
    float* Vs  = Sst + 64 * 68;        // [64][256] V   : [m][c]
    float* Ot  = smem;                 // reuse for epilogue: [256][68] (fits)

    const int tid = threadIdx.x;
    const int b  = blockIdx.y;
    const int n0 = blockIdx.x * QT;
    const int ty = tid >> 4;           // 0..15 -> rows 4*ty..4*ty+3
    const int tx = tid & 15;           // 0..15 -> col groups tx+16*cc, m-group tx

    // load Q transposed
    const float* Qg = g_q + ((size_t)b * HW + n0) * QKD;
    for (int idx = tid; idx < QT * QKD; idx += 256) {
        int r = idx >> 5, d = idx & 31;
        Qt[d * 68 + r] = Qg[idx];
    }

    ull acc[32];                       // [rr][8] : 4 rows x 16 cols packed
    #pragma unroll
    for (int i = 0; i < 32; i++) acc[i] = 0ull;
    float mrun[4] = {-1e30f, -1e30f, -1e30f, -1e30f};
    float lrun[4] = {0.f, 0.f, 0.f, 0.f};
    __syncthreads();

    for (int kt = 0; kt < HW / KT; kt++) {
        const int k0 = kt * KT;
        const float* Kg = g_k + ((size_t)b * HW + k0) * QKD;
        for (int idx = tid; idx < KT * QKD; idx += 256) {
            int m = idx >> 5, d = idx & 31;
            Kst[d * 68 + m] = Kg[idx];
        }
        const float4* Vg = (const float4*)(g_v + ((size_t)b * HW + k0) * NI);
        float4* Vs4 = (float4*)Vs;
        for (int idx = tid; idx < KT * NI / 4; idx += 256)
            Vs4[idx] = Vg[idx];
        __syncthreads();

        // ---- S = Q K^T : 4 rows x 4 m per thread, packed over m pairs ----
        ull s01[4], s23[4];
        #pragma unroll
        for (int rr = 0; rr < 4; rr++) { s01[rr] = 0ull; s23[rr] = 0ull; }
        #pragma unroll 4
        for (int d = 0; d < QKD; d++) {
            float4 q4 = *(const float4*)(Qt + d * 68 + 4 * ty);
            ulonglong2 k2 = *(const ulonglong2*)(Kst + d * 68 + 4 * tx);
            ull q0 = pack2(q4.x, q4.x), q1 = pack2(q4.y, q4.y);
            ull q2 = pack2(q4.z, q4.z), q3 = pack2(q4.w, q4.w);
            s01[0] = ffma2(q0, k2.x, s01[0]); s23[0] = ffma2(q0, k2.y, s23[0]);
            s01[1] = ffma2(q1, k2.x, s01[1]); s23[1] = ffma2(q1, k2.y, s23[1]);
            s01[2] = ffma2(q2, k2.x, s01[2]); s23[2] = ffma2(q2, k2.y, s23[2]);
            s01[3] = ffma2(q3, k2.x, s01[3]); s23[3] = ffma2(q3, k2.y, s23[3]);
        }

        // ---- online softmax (row stats across the 16 tx lanes) ----
        float px[4][4];
        #pragma unroll
        for (int rr = 0; rr < 4; rr++) {
            float sx0, sx1, sx2, sx3;
            unpack2(s01[rr], sx0, sx1);
            unpack2(s23[rr], sx2, sx3);
            float mloc = fmaxf(fmaxf(sx0, sx1), fmaxf(sx2, sx3));
            mloc = fmaxf(mloc, __shfl_xor_sync(0xffffffffu, mloc, 1));
            mloc = fmaxf(mloc, __shfl_xor_sync(0xffffffffu, mloc, 2));
            mloc = fmaxf(mloc, __shfl_xor_sync(0xffffffffu, mloc, 4));
            mloc = fmaxf(mloc, __shfl_xor_sync(0xffffffffu, mloc, 8));
            float mnew  = fmaxf(mrun[rr], mloc);
            float alpha = __expf(mrun[rr] - mnew);
            float p0 = __expf(sx0 - mnew), p1 = __expf(sx1 - mnew);
            float p2 = __expf(sx2 - mnew), p3 = __expf(sx3 - mnew);
            px[rr][0] = p0; px[rr][1] = p1; px[rr][2] = p2; px[rr][3] = p3;
            float ls = p0 + p1 + p2 + p3;
            ls += __shfl_xor_sync(0xffffffffu, ls, 1);
            ls += __shfl_xor_sync(0xffffffffu, ls, 2);
            ls += __shfl_xor_sync(0xffffffffu, ls, 4);
            ls += __shfl_xor_sync(0xffffffffu, ls, 8);
            lrun[rr] = lrun[rr] * alpha + ls;
            mrun[rr] = mnew;
            ull ap = pack2(alpha, alpha);
            #pragma unroll
            for (int i = 0; i < 8; i++) acc[rr * 8 + i] = fmul2(acc[rr * 8 + i], ap);
        }
        // publish P transposed: Sst[m][r]
        #pragma unroll
        for (int mm = 0; mm < 4; mm++) {
            float4 v = make_float4(px[0][mm], px[1][mm], px[2][mm], px[3][mm]);
            *(float4*)(Sst + (4 * tx + mm) * 68 + 4 * ty) = v;
        }
        __syncthreads();

        // ---- O += P V : 1 LDS.128 (p) + 4 LDS.128 (V) + 32 FMA2 per m ----
        #pragma unroll 2
        for (int m = 0; m < KT; m++) {
            float4 pv = *(const float4*)(Sst + m * 68 + 4 * ty);
            ull p0 = pack2(pv.x, pv.x), p1 = pack2(pv.y, pv.y);
            ull p2 = pack2(pv.z, pv.z), p3 = pack2(pv.w, pv.w);
            const ulonglong2* vr = (const ulonglong2*)(Vs + m * NI);
            #pragma unroll
            for (int cc = 0; cc < 4; cc++) {
                ulonglong2 v2 = vr[tx + 16 * cc];
                acc[0 * 8 + 2 * cc]     = ffma2(p0, v2.x, acc[0 * 8 + 2 * cc]);
                acc[0 * 8 + 2 * cc + 1] = ffma2(p0, v2.y, acc[0 * 8 + 2 * cc + 1]);
                acc[1 * 8 + 2 * cc]     = ffma2(p1, v2.x, acc[1 * 8 + 2 * cc]);
                acc[1 * 8 + 2 * cc + 1] = ffma2(p1, v2.y, acc[1 * 8 + 2 * cc + 1]);
                acc[2 * 8 + 2 * cc]     = ffma2(p2, v2.x, acc[2 * 8 + 2 * cc]);
                acc[2 * 8 + 2 * cc + 1] = ffma2(p2, v2.y, acc[2 * 8 + 2 * cc + 1]);
                acc[3 * 8 + 2 * cc]     = ffma2(p3, v2.x, acc[3 * 8 + 2 * cc]);
                acc[3 * 8 + 2 * cc + 1] = ffma2(p3, v2.y, acc[3 * 8 + 2 * cc + 1]);
            }
        }
        __syncthreads();
    }

    // ---- epilogue: normalize, transpose via SMEM, coalesced gamma*O + x ----
    float rinv[4];
    #pragma unroll
    for (int rr = 0; rr < 4; rr++) rinv[rr] = 1.f / lrun[rr];

    #pragma unroll
    for (int rr = 0; rr < 4; rr++) {
        #pragma unroll
        for (int cc = 0; cc < 4; cc++) {
            #pragma unroll
            for (int h = 0; h < 2; h++) {
                float o0, o1;
                unpack2(acc[rr * 8 + 2 * cc + h], o0, o1);
                int c0 = 4 * (tx + 16 * cc) + 2 * h;
                Ot[(size_t)c0 * 68 + 4 * ty + rr]       = o0 * rinv[rr];
                Ot[(size_t)(c0 + 1) * 68 + 4 * ty + rr] = o1 * rinv[rr];
            }
        }
    }
    __syncthreads();

    const float* xb = x   + (size_t)b * NI * HW;
    float*       ob = out + (size_t)b * NI * HW;
    #pragma unroll 4
    for (int pass = 0; pass < 16; pass++) {
        int c = pass * 16 + ty;
        float ga = gamma[c];
        float4 o = *(const float4*)(Ot + c * 68 + 4 * tx);
        size_t gi = (size_t)c * HW + n0 + 4 * tx;
        float4 xv = *(const float4*)(xb + gi);
        *(float4*)(ob + gi) = make_float4(ga * o.x + xv.x, ga * o.y + xv.y,
                                          ga * o.z + xv.z, ga * o.w + xv.w);
    }
}

extern "C" void kernel_launch(void* const* d_in, const int* in_sizes, int n_in,
                              void* d_out, int out_size)
{
    const float* x     = (const float*)d_in[0];
    const float* wq    = (const float*)d_in[1];
    const float* bq    = (const float*)d_in[2];
    const float* wk    = (const float*)d_in[3];
    const float* bk    = (const float*)d_in[4];
    const float* wv    = (const float*)d_in[5];
    const float* bv    = (const float*)d_in[6];
    const float* gamma = (const float*)d_in[7];
    float* out = (float*)d_out;

    const int smem_proj = (256 * 32 + 320 * 36) * 4;
    const int smem_attn = (32 * 68 + 32 * 68 + 64 * 68 + 64 * 256) * 4; // 91.6 KB
    cudaFuncSetAttribute(proj_kernel, cudaFuncAttributeMaxDynamicSharedMemorySize, smem_proj);
    cudaFuncSetAttribute(attn_kernel, cudaFuncAttributeMaxDynamicSharedMemorySize, smem_attn);

    proj_kernel<<<512, 256, smem_proj>>>(x, wq, bq, wk, bk, wv, bv);
    attn_kernel<<<dim3(HW / QT, BSZ), 256, smem_attn>>>(x, gamma, out);
}

// round 8
// speedup vs baseline: 6.7704x; 3.1497x over previous
#include <cuda_runtime.h>
#include <cuda_bf16.h>
#include <cstdint>

#define NI 256
#define QKD 32
#define BSZ 4
#define HW 4096
#define MQ 64
#define KV 64
#define NT (HW / KV)

typedef unsigned long long ull;

// Scratch: Q tf32 [b][n][32]; K tf32 in MMA1-B-fragment order [b][tile][2048];
// V bf16 [b][n][256] token-major.
__device__ uint32_t g_q[BSZ * HW * QKD];
__device__ uint32_t g_kf[BSZ * 64 * 2048];
__device__ uint32_t g_v[BSZ * HW * NI / 2];   // bf16 pairs

// ---- helpers ----
__device__ __forceinline__ ull pack2(float x, float y) {
    ull r; asm("mov.b64 %0, {%1, %2};" : "=l"(r) : "f"(x), "f"(y)); return r;
}
__device__ __forceinline__ void unpack2(ull v, float& x, float& y) {
    asm("mov.b64 {%0, %1}, %2;" : "=f"(x), "=f"(y) : "l"(v));
}
__device__ __forceinline__ ull ffma2(ull a, ull b, ull c) {
    ull d; asm("fma.rn.f32x2 %0, %1, %2, %3;" : "=l"(d) : "l"(a), "l"(b), "l"(c));
    return d;
}
__device__ __forceinline__ uint32_t smem_u32(const void* p) {
    uint32_t a;
    asm("{ .reg .u64 t; cvta.to.shared.u64 t, %1; cvt.u32.u64 %0, t; }" : "=r"(a) : "l"(p));
    return a;
}
__device__ __forceinline__ uint32_t cvt_tf32(float f) {
    uint32_t u; asm("cvt.rna.tf32.f32 %0, %1;" : "=r"(u) : "f"(f)); return u;
}
__device__ __forceinline__ uint32_t pack_bf16(float lo, float hi) {
    uint32_t d; asm("cvt.rn.bf16x2.f32 %0, %1, %2;" : "=r"(d) : "f"(hi), "f"(lo));
    return d;
}
__device__ __forceinline__ void cpa16(uint32_t dst, const void* src) {
    asm volatile("cp.async.cg.shared.global [%0], [%1], 16;" :: "r"(dst), "l"(src));
}
__device__ __forceinline__ void mma_tf32(float* c, const uint32_t* a, const uint32_t* b) {
    asm volatile("mma.sync.aligned.m16n8k8.row.col.f32.tf32.tf32.f32 "
        "{%0,%1,%2,%3}, {%4,%5,%6,%7}, {%8,%9}, {%0,%1,%2,%3};"
        : "+f"(c[0]), "+f"(c[1]), "+f"(c[2]), "+f"(c[3])
        : "r"(a[0]), "r"(a[1]), "r"(a[2]), "r"(a[3]), "r"(b[0]), "r"(b[1]));
}
__device__ __forceinline__ void mma_bf16(float* c, const uint32_t* a, const uint32_t* b) {
    asm volatile("mma.sync.aligned.m16n8k16.row.col.f32.bf16.bf16.f32 "
        "{%0,%1,%2,%3}, {%4,%5,%6,%7}, {%8,%9}, {%0,%1,%2,%3};"
        : "+f"(c[0]), "+f"(c[1]), "+f"(c[2]), "+f"(c[3])
        : "r"(a[0]), "r"(a[1]), "r"(a[2]), "r"(a[3]), "r"(b[0]), "r"(b[1]));
}
__device__ __forceinline__ void ldm_x4(uint32_t* r, uint32_t addr) {
    asm volatile("ldmatrix.sync.aligned.m8n8.x4.shared.b16 {%0,%1,%2,%3}, [%4];"
        : "=r"(r[0]), "=r"(r[1]), "=r"(r[2]), "=r"(r[3]) : "r"(addr));
}
__device__ __forceinline__ void ldm_x4t(uint32_t* r, uint32_t addr) {
    asm volatile("ldmatrix.sync.aligned.m8n8.x4.trans.shared.b16 {%0,%1,%2,%3}, [%4];"
        : "=r"(r[0]), "=r"(r[1]), "=r"(r[2]), "=r"(r[3]) : "r"(addr));
}

// SMEM map (bytes) for attn kernel
#define VS_OFF   0u          // 2 x 64 x 528 = 67584
#define VBUF     33792u
#define KF_OFF   67584u      // 2 x 8192 = 16384
#define QF_OFF   83968u      // 8192
#define PB_OFF   92160u      // 64 x 144 = 9216
#define LSH_OFF  101376u     // 4 x 64 x 4 = 1024
#define RIV_OFF  102400u     // 64 x 4
#define SMEM_ATTN 102656
#define OS_OFF   0u          // overlay on VS: 64 x 258 x 4 = 66048

// ---------------------------------------------------------------------------
// Projection: per block 32 tokens x 320 outputs, 2-output register blocking.
// Emits tf32 Q (token-major), tf32 K (MMA1 B-frag order), bf16 V (token-major).
// ---------------------------------------------------------------------------
__global__ __launch_bounds__(256, 2)
void proj_kernel(const float* __restrict__ x,
                 const float* __restrict__ wq, const float* __restrict__ bq,
                 const float* __restrict__ wk, const float* __restrict__ bk,
                 const float* __restrict__ wv, const float* __restrict__ bv)
{
    extern __shared__ float smemf[];
    float* xs = smemf;             // [256][32]
    float* ys = smemf + 256 * 32;  // [320][36]

    const int tid = threadIdx.x;
    const int blk = blockIdx.x;
    const int b  = blk >> 7;
    const int n0 = (blk & 127) * 32;
    const float* xb = x + (size_t)b * NI * HW;

    for (int idx = tid; idx < 256 * 32; idx += 256) {
        int c = idx >> 5, t = idx & 31;
        xs[idx] = xb[(size_t)c * HW + n0 + t];
    }
    __syncthreads();

    const int oslot = tid >> 3;   // 0..31
    const int tq    = tid & 7;
    const ulonglong2* xs2 = (const ulonglong2*)xs;

    for (int i = 0; i < 5; i++) {
        int o0 = 2 * oslot + 64 * i;
        const float *wr0, *wr1; float bi0, bi1;
        if (o0 < 32)      { wr0 = wq + o0 * NI;        bi0 = bq[o0];
                            wr1 = wq + (o0+1) * NI;    bi1 = bq[o0+1]; }
        else if (o0 < 64) { wr0 = wk + (o0-32) * NI;   bi0 = bk[o0-32];
                            wr1 = wk + (o0-31) * NI;   bi1 = bk[o0-31]; }
        else              { wr0 = wv + (o0-64) * NI;   bi0 = bv[o0-64];
                            wr1 = wv + (o0-63) * NI;   bi1 = bv[o0-63]; }
        ull a01_0 = pack2(bi0, bi0), a23_0 = a01_0;
        ull a01_1 = pack2(bi1, bi1), a23_1 = a01_1;
        #pragma unroll 4
        for (int c = 0; c < NI; c++) {
            float w0 = __ldg(wr0 + c), w1 = __ldg(wr1 + c);
            ull wp0 = pack2(w0, w0), wp1 = pack2(w1, w1);
            ulonglong2 xv = xs2[c * 8 + tq];
            a01_0 = ffma2(wp0, xv.x, a01_0);
            a23_0 = ffma2(wp0, xv.y, a23_0);
            a01_1 = ffma2(wp1, xv.x, a01_1);
            a23_1 = ffma2(wp1, xv.y, a23_1);
        }
        float4 r0, r1;
        unpack2(a01_0, r0.x, r0.y); unpack2(a23_0, r0.z, r0.w);
        unpack2(a01_1, r1.x, r1.y); unpack2(a23_1, r1.z, r1.w);
        ((float4*)(ys + o0 * 36))[tq] = r0;
        ((float4*)(ys + (o0 + 1) * 36))[tq] = r1;
    }
    __syncthreads();

    // Q: tf32, token-major, coalesced
    uint32_t* gq = g_q + ((size_t)b * HW + n0) * QKD;
    for (int idx = tid; idx < 32 * QKD; idx += 256) {
        int n = idx >> 5, o = idx & 31;
        gq[idx] = cvt_tf32(ys[o * 36 + n]);
    }
    // K: tf32, B-fragment order: tile stride 2048 words; [jg][s][lane]{d0, d0+4}
    {
        const int lane = tid & 31;
        const int jb = (n0 & 32) >> 3;
        #pragma unroll
        for (int it = 0; it < 2; it++) {
            int pp = (tid >> 5) + 8 * it;
            int jl = pp >> 2, s = pp & 3;
            int nloc = 8 * jl + (lane >> 2);
            int d0 = 8 * s + (lane & 3);
            uint2 v;
            v.x = cvt_tf32(ys[(32 + d0) * 36 + nloc]);
            v.y = cvt_tf32(ys[(36 + d0) * 36 + nloc]);
            size_t dst = ((size_t)(b * 64 + (n0 >> 6))) * 2048 +
                         ((jb + jl) * 128 + s * 32 + lane) * 2;
            *(uint2*)(g_kf + dst) = v;
        }
    }
    // V: bf16, token-major
    uint32_t* gv = g_v + ((size_t)b * HW + n0) * (NI / 2);
    for (int idx = tid; idx < 32 * 128; idx += 256) {
        int n = idx >> 7, c2 = idx & 127;
        gv[(size_t)n * 128 + c2] =
            pack_bf16(ys[(64 + 2 * c2) * 36 + n], ys[(65 + 2 * c2) * 36 + n]);
    }
}

// ---------------------------------------------------------------------------
// mma.sync attention: 64 queries/CTA, 8 warps (2 m-groups x 4 n-groups).
// S = QK^T in tf32, P = exp(S) unnormalized -> bf16 SMEM, O += P V in bf16.
// ---------------------------------------------------------------------------
__device__ __forceinline__ void load_tile(uint32_t sb, const uint32_t* kfb,
                                          const uint32_t* vbb, int t, int buf) {
    const int tid = threadIdx.x;
    const uint32_t* ksrc = kfb + (size_t)t * 2048;
    uint32_t kd = sb + KF_OFF + buf * 8192;
    cpa16(kd + tid * 16, ksrc + tid * 4);
    cpa16(kd + 4096 + tid * 16, ksrc + 1024 + tid * 4);
    const uint32_t* vsrc = vbb + (size_t)t * 64 * 128;
    uint32_t vd = sb + VS_OFF + buf * VBUF;
    #pragma unroll
    for (int k = 0; k < 8; k++) {
        int i = tid + 256 * k;
        int row = i >> 5, c16 = i & 31;
        cpa16(vd + row * 528 + c16 * 16, vsrc + (size_t)row * 128 + c16 * 4);
    }
    asm volatile("cp.async.commit_group;" ::: "memory");
}

__global__ __launch_bounds__(256, 2)
void attn_kernel(const float* __restrict__ x, const float* __restrict__ gamma,
                 float* __restrict__ out)
{
    extern __shared__ char smem[];
    const uint32_t sb = smem_u32(smem);

    const int tid  = threadIdx.x;
    const int wid  = tid >> 5;
    const int lane = tid & 31;
    const int wm = wid >> 2, wn = wid & 3;
    const int tq = lane >> 2, tc = lane & 3;
    const int b  = blockIdx.y;
    const int n0 = blockIdx.x * MQ;

    // build Q fragment table in SMEM (one-time)
    {
        const uint32_t* Qg = g_q + ((size_t)b * HW + n0) * QKD;
        #pragma unroll
        for (int u = 0; u < 8; u++) {
            int flat = tid * 8 + u;
            int a = flat & 3, t = (flat >> 2) & 31, s = (flat >> 7) & 3, mt = flat >> 9;
            int row = 16 * mt + ((t >> 2) & 7) + 8 * (a & 1);
            int col = 8 * s + (t & 3) + 4 * (a >> 1);
            uint32_t v = Qg[row * 32 + col];
            asm volatile("st.shared.b32 [%0], %1;" :: "r"(sb + QF_OFF + flat * 4), "r"(v) : "memory");
        }
    }

    const uint32_t* kfb = g_kf + (size_t)b * 64 * 2048;
    const uint32_t* vbb = g_v + (size_t)b * HW * 128;
    load_tile(sb, kfb, vbb, 0, 0);

    float oacc[2][8][4];
    #pragma unroll
    for (int i = 0; i < 2; i++)
        #pragma unroll
        for (int j = 0; j < 8; j++)
            #pragma unroll
            for (int k = 0; k < 4; k++) oacc[i][j][k] = 0.f;
    float rs[2][2] = {{0.f, 0.f}, {0.f, 0.f}};

    const int m8  = (lane >> 3) & 1;
    const int m16 = (lane >> 4) & 1;
    const int l7  = lane & 7;

    for (int t = 0; t < NT; t++) {
        const int buf = t & 1;
        asm volatile("cp.async.wait_group 0;" ::: "memory");
        __syncthreads();
        if (t + 1 < NT) load_tile(sb, kfb, vbb, t + 1, buf ^ 1);

        // ---- MMA1: S[2 m-tiles][2 n-tiles] over k=32 (tf32) ----
        float sa[2][2][4];
        #pragma unroll
        for (int i = 0; i < 2; i++)
            #pragma unroll
            for (int j = 0; j < 2; j++)
                #pragma unroll
                for (int k = 0; k < 4; k++) sa[i][j][k] = 0.f;
        #pragma unroll
        for (int s = 0; s < 4; s++) {
            uint32_t qa[2][4], kb[2][2];
            #pragma unroll
            for (int mt = 0; mt < 2; mt++)
                asm volatile("ld.shared.v4.b32 {%0,%1,%2,%3}, [%4];"
                    : "=r"(qa[mt][0]), "=r"(qa[mt][1]), "=r"(qa[mt][2]), "=r"(qa[mt][3])
                    : "r"(sb + QF_OFF + (((2 * wm + mt) * 4 + s) * 32 + lane) * 16));
            #pragma unroll
            for (int jj = 0; jj < 2; jj++)
                asm volatile("ld.shared.v2.b32 {%0,%1}, [%2];"
                    : "=r"(kb[jj][0]), "=r"(kb[jj][1])
                    : "r"(sb + KF_OFF + buf * 8192 + ((2 * wn + jj) * 128 + s * 32 + lane) * 8));
            #pragma unroll
            for (int mt = 0; mt < 2; mt++)
                #pragma unroll
                for (int jj = 0; jj < 2; jj++)
                    mma_tf32(sa[mt][jj], qa[mt], kb[jj]);
        }

        // ---- exp + row sums + pack bf16 + store P ----
        #pragma unroll
        for (int mt = 0; mt < 2; mt++) {
            int row = 32 * wm + 16 * mt + tq;
            #pragma unroll
            for (int jj = 0; jj < 2; jj++) {
                float p0 = __expf(sa[mt][jj][0]);
                float p1 = __expf(sa[mt][jj][1]);
                float p2 = __expf(sa[mt][jj][2]);
                float p3 = __expf(sa[mt][jj][3]);
                rs[mt][0] += p0 + p1;
                rs[mt][1] += p2 + p3;
                uint32_t lo = pack_bf16(p0, p1);
                uint32_t hi = pack_bf16(p2, p3);
                uint32_t colb = (8 * (2 * wn + jj) + 2 * tc) * 2;
                asm volatile("st.shared.b32 [%0], %1;" ::
                    "r"(sb + PB_OFF + row * 144 + colb), "r"(lo) : "memory");
                asm volatile("st.shared.b32 [%0], %1;" ::
                    "r"(sb + PB_OFF + (row + 8) * 144 + colb), "r"(hi) : "memory");
            }
        }
        __syncthreads();

        // ---- MMA2: O[32 x 128] += P[32 x 64] V[64 x 128] (bf16) ----
        const uint32_t vbase = sb + VS_OFF + buf * VBUF;
        #pragma unroll
        for (int ks = 0; ks < 4; ks++) {
            uint32_t pa[2][4];
            #pragma unroll
            for (int mt = 0; mt < 2; mt++)
                ldm_x4(pa[mt], sb + PB_OFF +
                    (32 * wm + 16 * mt + l7 + 8 * m8) * 144 + ks * 32 + m16 * 16);
            #pragma unroll
            for (int ntp = 0; ntp < 4; ntp++) {
                uint32_t vb[4];
                ldm_x4t(vb, vbase + (16 * ks + 8 * m8 + l7) * 528 +
                            (64 * wn + 16 * ntp + 8 * m16) * 2);
                #pragma unroll
                for (int mt = 0; mt < 2; mt++) {
                    mma_bf16(oacc[mt][2 * ntp], pa[mt], vb);
                    mma_bf16(oacc[mt][2 * ntp + 1], pa[mt], vb + 2);
                }
            }
        }
    }

    // ---- l reduction across lanes/warps ----
    #pragma unroll
    for (int mt = 0; mt < 2; mt++)
        #pragma unroll
        for (int h = 0; h < 2; h++) {
            float v = rs[mt][h];
            v += __shfl_xor_sync(0xffffffffu, v, 1);
            v += __shfl_xor_sync(0xffffffffu, v, 2);
            if (tc == 0) {
                int row = 32 * wm + 16 * mt + 8 * h + tq;
                asm volatile("st.shared.f32 [%0], %1;" ::
                    "r"(sb + LSH_OFF + (wn * 64 + row) * 4), "f"(v) : "memory");
            }
        }
    __syncthreads();   // also: all MMA2 reads of Vs done before Os overlay
    if (tid < 64) {
        float s = 0.f;
        #pragma unroll
        for (int w = 0; w < 4; w++) {
            float v;
            asm volatile("ld.shared.f32 %0, [%1];" : "=f"(v)
                : "r"(sb + LSH_OFF + (w * 64 + tid) * 4));
            s += v;
        }
        float riv = 1.f / s;
        asm volatile("st.shared.f32 [%0], %1;" ::
            "r"(sb + RIV_OFF + tid * 4), "f"(riv) : "memory");
    }

    // ---- stage O to SMEM (transpose), pitch 258 floats ----
    #pragma unroll
    for (int mt = 0; mt < 2; mt++) {
        int row = 32 * wm + 16 * mt + tq;
        #pragma unroll
        for (int nt = 0; nt < 8; nt++) {
            int col = 64 * wn + 8 * nt + 2 * tc;
            asm volatile("st.shared.v2.f32 [%0], {%1,%2};" ::
                "r"(sb + OS_OFF + (row * 258 + col) * 4),
                "f"(oacc[mt][nt][0]), "f"(oacc[mt][nt][1]) : "memory");
            asm volatile("st.shared.v2.f32 [%0], {%1,%2};" ::
                "r"(sb + OS_OFF + ((row + 8) * 258 + col) * 4),
                "f"(oacc[mt][nt][2]), "f"(oacc[mt][nt][3]) : "memory");
        }
    }
    __syncthreads();

    // ---- coalesced epilogue: out = gamma*O/l + x ----
    const float* xb = x   + (size_t)b * NI * HW;
    float*       ob = out + (size_t)b * NI * HW;
    for (int cc = wid; cc < NI; cc += 8) {
        float ga = __ldg(gamma + cc);
        #pragma unroll
        for (int h = 0; h < 2; h++) {
            int n = lane + 32 * h;
            float riv, o;
            asm volatile("ld.shared.f32 %0, [%1];" : "=f"(riv)
                : "r"(sb + RIV_OFF + n * 4));
            asm volatile("ld.shared.f32 %0, [%1];" : "=f"(o)
                : "r"(sb + OS_OFF + (n * 258 + cc) * 4));
            size_t gi = (size_t)cc * HW + n0 + n;
            ob[gi] = ga * (o * riv) + xb[gi];
        }
    }
}

extern "C" void kernel_launch(void* const* d_in, const int* in_sizes, int n_in,
                              void* d_out, int out_size)
{
    const float* x     = (const float*)d_in[0];
    const float* wq    = (const float*)d_in[1];
    const float* bq    = (const float*)d_in[2];
    const float* wk    = (const float*)d_in[3];
    const float* bk    = (const float*)d_in[4];
    const float* wv    = (const float*)d_in[5];
    const float* bv    = (const float*)d_in[6];
    const float* gamma = (const float*)d_in[7];
    float* out = (float*)d_out;

    const int smem_proj = (256 * 32 + 320 * 36) * 4;
    cudaFuncSetAttribute(proj_kernel, cudaFuncAttributeMaxDynamicSharedMemorySize, smem_proj);
    cudaFuncSetAttribute(attn_kernel, cudaFuncAttributeMaxDynamicSharedMemorySize, SMEM_ATTN);

    proj_kernel<<<512, 256, smem_proj>>>(x, wq, bq, wk, bk, wv, bv);
    attn_kernel<<<dim3(HW / MQ, BSZ), 256, SMEM_ATTN>>>(x, gamma, out);
}

// round 9
// speedup vs baseline: 13.5890x; 2.0071x over previous
#include <cuda_runtime.h>
#include <cuda_bf16.h>
#include <cstdint>

#define NI 256
#define QKD 32
#define BSZ 4
#define HW 4096
#define MQ 64
#define KV 64
#define NT (HW / KV)

typedef unsigned long long ull;

// Scratch: Q tf32 [b][n][32]; K tf32 in MMA1-B-fragment order [b][tile][2048];
// V bf16 [b][n][256] token-major.
__device__ uint32_t g_q[BSZ * HW * QKD];
__device__ uint32_t g_kf[BSZ * 64 * 2048];
__device__ uint32_t g_v[BSZ * HW * NI / 2];   // bf16 pairs

// ---- helpers ----
__device__ __forceinline__ uint32_t smem_u32(const void* p) {
    uint32_t a;
    asm("{ .reg .u64 t; cvta.to.shared.u64 t, %1; cvt.u32.u64 %0, t; }" : "=r"(a) : "l"(p));
    return a;
}
__device__ __forceinline__ uint32_t cvt_tf32(float f) {
    uint32_t u; asm("cvt.rna.tf32.f32 %0, %1;" : "=r"(u) : "f"(f)); return u;
}
__device__ __forceinline__ uint32_t pack_bf16(float lo, float hi) {
    uint32_t d; asm("cvt.rn.bf16x2.f32 %0, %1, %2;" : "=r"(d) : "f"(hi), "f"(lo));
    return d;
}
__device__ __forceinline__ void cpa16(uint32_t dst, const void* src) {
    asm volatile("cp.async.cg.shared.global [%0], [%1], 16;" :: "r"(dst), "l"(src));
}
__device__ __forceinline__ void mma_tf32(float* c, const uint32_t* a, const uint32_t* b) {
    asm volatile("mma.sync.aligned.m16n8k8.row.col.f32.tf32.tf32.f32 "
        "{%0,%1,%2,%3}, {%4,%5,%6,%7}, {%8,%9}, {%0,%1,%2,%3};"
        : "+f"(c[0]), "+f"(c[1]), "+f"(c[2]), "+f"(c[3])
        : "r"(a[0]), "r"(a[1]), "r"(a[2]), "r"(a[3]), "r"(b[0]), "r"(b[1]));
}
__device__ __forceinline__ void mma_bf16(float* c, const uint32_t* a, const uint32_t* b) {
    asm volatile("mma.sync.aligned.m16n8k16.row.col.f32.bf16.bf16.f32 "
        "{%0,%1,%2,%3}, {%4,%5,%6,%7}, {%8,%9}, {%0,%1,%2,%3};"
        : "+f"(c[0]), "+f"(c[1]), "+f"(c[2]), "+f"(c[3])
        : "r"(a[0]), "r"(a[1]), "r"(a[2]), "r"(a[3]), "r"(b[0]), "r"(b[1]));
}
__device__ __forceinline__ void ldm_x4(uint32_t* r, uint32_t addr) {
    asm volatile("ldmatrix.sync.aligned.m8n8.x4.shared.b16 {%0,%1,%2,%3}, [%4];"
        : "=r"(r[0]), "=r"(r[1]), "=r"(r[2]), "=r"(r[3]) : "r"(addr));
}
__device__ __forceinline__ void ldm_x4t(uint32_t* r, uint32_t addr) {
    asm volatile("ldmatrix.sync.aligned.m8n8.x4.trans.shared.b16 {%0,%1,%2,%3}, [%4];"
        : "=r"(r[0]), "=r"(r[1]), "=r"(r[2]), "=r"(r[3]) : "r"(addr));
}

// ===========================================================================
// proj kernel v2: tensor-core GEMM, 64 outch x 256 tokens per CTA.
// ===========================================================================
#define PW_OFF   0u          // Wf fragment-ordered: 16384 words = 65536 B
#define PX_OFF   65536u      // X chunks: 2 x (32 x 264 floats) = 67584 B
#define PXBUF    33792u      // 32 * 264 * 4
#define PBI_OFF  133120u     // bias 64 floats
#define SMEM_PROJ 133376
// epilogue overlay on PX: Ot[n(256)][o(64)] pitch 65 floats = 66560 B

__device__ __forceinline__ void load_xchunk(uint32_t sb, const float* xb, int kc, int buf) {
    const int tid = threadIdx.x;
    uint32_t dst = sb + PX_OFF + buf * PXBUF;
    #pragma unroll
    for (int k = 0; k < 8; k++) {
        int i = tid + 256 * k;          // 0..2047
        int cr = i >> 6, c16 = i & 63;
        cpa16(dst + cr * 1056 + c16 * 16,
              xb + (size_t)(kc * 32 + cr) * HW + c16 * 4);
    }
    asm volatile("cp.async.commit_group;" ::: "memory");
}

__global__ __launch_bounds__(256, 1)
void proj_kernel(const float* __restrict__ x,
                 const float* __restrict__ wq, const float* __restrict__ bq,
                 const float* __restrict__ wk, const float* __restrict__ bk,
                 const float* __restrict__ wv, const float* __restrict__ bv)
{
    extern __shared__ char smem[];
    const uint32_t sb = smem_u32(smem);
    float* Ot     = (float*)(smem + PX_OFF);
    float* Xtmp   = (float*)(smem + PX_OFF);
    float* bias_s = (float*)(smem + PBI_OFF);
    uint32_t* Wf  = (uint32_t*)(smem + PW_OFF);

    const int tid = threadIdx.x;
    const int wid = tid >> 5, lane = tid & 31;
    const int wm = wid >> 2, wn = wid & 3;
    const int tq = lane >> 2, tc = lane & 3;
    const int nt0 = blockIdx.x * 256;
    const int ot  = blockIdx.y;          // 0..4
    const int b   = blockIdx.z;

    if (tid < 64) {
        int og = ot * 64 + tid;
        bias_s[tid] = (og < 32) ? bq[og] : (og < 64) ? bk[og - 32] : bv[og - 64];
    }

    // ---- W: coalesced natural load into Xtmp [o][c] pitch 264 ----
    #pragma unroll
    for (int k = 0; k < 16; k++) {
        int idx = tid + 256 * k;         // 0..4095
        int o = idx >> 6, c4 = idx & 63;
        int og = ot * 64 + o;
        const float* wr = (og < 32) ? wq + og * NI
                        : (og < 64) ? wk + (og - 32) * NI
                                    : wv + (og - 64) * NI;
        *(float4*)((char*)Xtmp + o * 1056 + c4 * 16) = __ldg((const float4*)(wr) + c4);
    }
    __syncthreads();
    // ---- rearrange to A-fragment order (tf32) ----
    #pragma unroll
    for (int k = 0; k < 64; k++) {
        int flat = tid + 256 * k;        // 0..16383
        int a  = flat & 3;
        int ln = (flat >> 2) & 31;
        int s  = (flat >> 7) & 31;
        int mt = flat >> 12;
        int ol = 16 * mt + (ln >> 2) + 8 * (a & 1);
        int c  = 8 * s + (ln & 3) + 4 * (a >> 1);
        Wf[flat] = cvt_tf32(*(const float*)((char*)Xtmp + ol * 1056 + c * 4));
    }
    __syncthreads();

    // ---- mainloop ----
    const float* xb = x + (size_t)b * NI * HW + nt0;
    load_xchunk(sb, xb, 0, 0);

    float oacc[2][8][4];
    #pragma unroll
    for (int i = 0; i < 2; i++)
        #pragma unroll
        for (int j = 0; j < 8; j++)
            #pragma unroll
            for (int e = 0; e < 4; e++) oacc[i][j][e] = 0.f;

    for (int kc = 0; kc < 8; kc++) {
        const int buf = kc & 1;
        asm volatile("cp.async.wait_group 0;" ::: "memory");
        __syncthreads();
        if (kc + 1 < 8) load_xchunk(sb, xb, kc + 1, buf ^ 1);
        const uint32_t xbase = sb + PX_OFF + buf * PXBUF;

        #pragma unroll
        for (int ks = 0; ks < 4; ks++) {
            const int sg = kc * 4 + ks;
            uint32_t qa[2][4];
            #pragma unroll
            for (int mt = 0; mt < 2; mt++)
                asm volatile("ld.shared.v4.b32 {%0,%1,%2,%3}, [%4];"
                    : "=r"(qa[mt][0]), "=r"(qa[mt][1]), "=r"(qa[mt][2]), "=r"(qa[mt][3])
                    : "r"(sb + PW_OFF + (uint32_t)((((2*wm+mt)*32 + sg)*32 + lane) * 16)));
            #pragma unroll
            for (int ntp = 0; ntp < 8; ntp++) {
                int n = 64 * wn + 8 * ntp + tq;
                float f0, f1;
                asm volatile("ld.shared.f32 %0, [%1];" : "=f"(f0)
                    : "r"(xbase + (uint32_t)(((ks*8 + tc) * 264 + n) * 4)));
                asm volatile("ld.shared.f32 %0, [%1];" : "=f"(f1)
                    : "r"(xbase + (uint32_t)(((ks*8 + tc + 4) * 264 + n) * 4)));
                uint32_t bb[2] = { cvt_tf32(f0), cvt_tf32(f1) };
                mma_tf32(oacc[0][ntp], qa[0], bb);
                mma_tf32(oacc[1][ntp], qa[1], bb);
            }
        }
    }
    __syncthreads();   // all reads of X buffers done before Ot overlay

    // ---- stage Ot[n][o] (pitch 65) with bias ----
    #pragma unroll
    for (int mt = 0; mt < 2; mt++) {
        int o0 = 32 * wm + 16 * mt + tq;
        float b0 = bias_s[o0], b1 = bias_s[o0 + 8];
        #pragma unroll
        for (int ntp = 0; ntp < 8; ntp++) {
            int n = 64 * wn + 8 * ntp + 2 * tc;
            Ot[n * 65 + o0]           = oacc[mt][ntp][0] + b0;
            Ot[(n + 1) * 65 + o0]     = oacc[mt][ntp][1] + b0;
            Ot[n * 65 + o0 + 8]       = oacc[mt][ntp][2] + b1;
            Ot[(n + 1) * 65 + o0 + 8] = oacc[mt][ntp][3] + b1;
        }
    }
    __syncthreads();

    // ---- write out ----
    if (ot == 0) {
        // Q: tf32 token-major
        uint32_t* gq = g_q + ((size_t)b * HW + nt0) * QKD;
        #pragma unroll 4
        for (int j = 0; j < 32; j++) {
            int n = wid + 8 * j;
            gq[(size_t)n * QKD + lane] = cvt_tf32(Ot[n * 65 + lane]);
        }
        // K: frag order, 4 key-tiles of 64
        #pragma unroll
        for (int p = 0; p < 2; p++) {
            int combo = wid + 8 * p;          // 0..15
            int ktile = combo >> 2, s = combo & 3;
            #pragma unroll 4
            for (int jg = 0; jg < 8; jg++) {
                int n  = ktile * 64 + 8 * jg + (lane >> 2);
                int d0 = 8 * s + (lane & 3);
                uint2 v;
                v.x = cvt_tf32(Ot[n * 65 + 32 + d0]);
                v.y = cvt_tf32(Ot[n * 65 + 36 + d0]);
                *(uint2*)(g_kf + (size_t)(b * 64 + (nt0 >> 6) + ktile) * 2048
                          + (jg * 128 + s * 32 + lane) * 2) = v;
            }
        }
    } else {
        // V: bf16 pairs token-major; this tile covers c2 slots (ot-1)*32 .. +31
        uint32_t* gv = g_v + ((size_t)b * HW + nt0) * 128 + (ot - 1) * 32;
        #pragma unroll 4
        for (int j = 0; j < 32; j++) {
            int n = wid + 8 * j;
            float v0 = Ot[n * 65 + 2 * lane];
            float v1 = Ot[n * 65 + 2 * lane + 1];
            gv[(size_t)n * 128 + lane] = pack_bf16(v0, v1);
        }
    }
}

// ===========================================================================
// attn kernel (unchanged from R7/R8 — passing at 166.8us)
// ===========================================================================
#define VS_OFF   0u          // 2 x 64 x 528 = 67584
#define VBUF     33792u
#define KF_OFF   67584u      // 2 x 8192 = 16384
#define QF_OFF   83968u      // 8192
#define PB_OFF   92160u      // 64 x 144 = 9216
#define LSH_OFF  101376u     // 4 x 64 x 4 = 1024
#define RIV_OFF  102400u     // 64 x 4
#define SMEM_ATTN 102656
#define OS_OFF   0u          // overlay on VS: 64 x 258 x 4 = 66048

__device__ __forceinline__ void load_tile(uint32_t sb, const uint32_t* kfb,
                                          const uint32_t* vbb, int t, int buf) {
    const int tid = threadIdx.x;
    const uint32_t* ksrc = kfb + (size_t)t * 2048;
    uint32_t kd = sb + KF_OFF + buf * 8192;
    cpa16(kd + tid * 16, ksrc + tid * 4);
    cpa16(kd + 4096 + tid * 16, ksrc + 1024 + tid * 4);
    const uint32_t* vsrc = vbb + (size_t)t * 64 * 128;
    uint32_t vd = sb + VS_OFF + buf * VBUF;
    #pragma unroll
    for (int k = 0; k < 8; k++) {
        int i = tid + 256 * k;
        int row = i >> 5, c16 = i & 31;
        cpa16(vd + row * 528 + c16 * 16, vsrc + (size_t)row * 128 + c16 * 4);
    }
    asm volatile("cp.async.commit_group;" ::: "memory");
}

__global__ __launch_bounds__(256, 2)
void attn_kernel(const float* __restrict__ x, const float* __restrict__ gamma,
                 float* __restrict__ out)
{
    extern __shared__ char smem[];
    const uint32_t sb = smem_u32(smem);

    const int tid  = threadIdx.x;
    const int wid  = tid >> 5;
    const int lane = tid & 31;
    const int wm = wid >> 2, wn = wid & 3;
    const int tq = lane >> 2, tc = lane & 3;
    const int b  = blockIdx.y;
    const int n0 = blockIdx.x * MQ;

    {
        const uint32_t* Qg = g_q + ((size_t)b * HW + n0) * QKD;
        #pragma unroll
        for (int u = 0; u < 8; u++) {
            int flat = tid * 8 + u;
            int a = flat & 3, t = (flat >> 2) & 31, s = (flat >> 7) & 3, mt = flat >> 9;
            int row = 16 * mt + ((t >> 2) & 7) + 8 * (a & 1);
            int col = 8 * s + (t & 3) + 4 * (a >> 1);
            uint32_t v = Qg[row * 32 + col];
            asm volatile("st.shared.b32 [%0], %1;" :: "r"(sb + QF_OFF + flat * 4), "r"(v) : "memory");
        }
    }

    const uint32_t* kfb = g_kf + (size_t)b * 64 * 2048;
    const uint32_t* vbb = g_v + (size_t)b * HW * 128;
    load_tile(sb, kfb, vbb, 0, 0);

    float oacc[2][8][4];
    #pragma unroll
    for (int i = 0; i < 2; i++)
        #pragma unroll
        for (int j = 0; j < 8; j++)
            #pragma unroll
            for (int k = 0; k < 4; k++) oacc[i][j][k] = 0.f;
    float rs[2][2] = {{0.f, 0.f}, {0.f, 0.f}};

    const int m8  = (lane >> 3) & 1;
    const int m16 = (lane >> 4) & 1;
    const int l7  = lane & 7;

    for (int t = 0; t < NT; t++) {
        const int buf = t & 1;
        asm volatile("cp.async.wait_group 0;" ::: "memory");
        __syncthreads();
        if (t + 1 < NT) load_tile(sb, kfb, vbb, t + 1, buf ^ 1);

        float sa[2][2][4];
        #pragma unroll
        for (int i = 0; i < 2; i++)
            #pragma unroll
            for (int j = 0; j < 2; j++)
                #pragma unroll
                for (int k = 0; k < 4; k++) sa[i][j][k] = 0.f;
        #pragma unroll
        for (int s = 0; s < 4; s++) {
            uint32_t qa[2][4], kb[2][2];
            #pragma unroll
            for (int mt = 0; mt < 2; mt++)
                asm volatile("ld.shared.v4.b32 {%0,%1,%2,%3}, [%4];"
                    : "=r"(qa[mt][0]), "=r"(qa[mt][1]), "=r"(qa[mt][2]), "=r"(qa[mt][3])
                    : "r"(sb + QF_OFF + (((2 * wm + mt) * 4 + s) * 32 + lane) * 16));
            #pragma unroll
            for (int jj = 0; jj < 2; jj++)
                asm volatile("ld.shared.v2.b32 {%0,%1}, [%2];"
                    : "=r"(kb[jj][0]), "=r"(kb[jj][1])
                    : "r"(sb + KF_OFF + buf * 8192 + ((2 * wn + jj) * 128 + s * 32 + lane) * 8));
            #pragma unroll
            for (int mt = 0; mt < 2; mt++)
                #pragma unroll
                for (int jj = 0; jj < 2; jj++)
                    mma_tf32(sa[mt][jj], qa[mt], kb[jj]);
        }

        #pragma unroll
        for (int mt = 0; mt < 2; mt++) {
            int row = 32 * wm + 16 * mt + tq;
            #pragma unroll
            for (int jj = 0; jj < 2; jj++) {
                float p0 = __expf(sa[mt][jj][0]);
                float p1 = __expf(sa[mt][jj][1]);
                float p2 = __expf(sa[mt][jj][2]);
                float p3 = __expf(sa[mt][jj][3]);
                rs[mt][0] += p0 + p1;
                rs[mt][1] += p2 + p3;
                uint32_t lo = pack_bf16(p0, p1);
                uint32_t hi = pack_bf16(p2, p3);
                uint32_t colb = (8 * (2 * wn + jj) + 2 * tc) * 2;
                asm volatile("st.shared.b32 [%0], %1;" ::
                    "r"(sb + PB_OFF + row * 144 + colb), "r"(lo) : "memory");
                asm volatile("st.shared.b32 [%0], %1;" ::
                    "r"(sb + PB_OFF + (row + 8) * 144 + colb), "r"(hi) : "memory");
            }
        }
        __syncthreads();

        const uint32_t vbase = sb + VS_OFF + buf * VBUF;
        #pragma unroll
        for (int ks = 0; ks < 4; ks++) {
            uint32_t pa[2][4];
            #pragma unroll
            for (int mt = 0; mt < 2; mt++)
                ldm_x4(pa[mt], sb + PB_OFF +
                    (32 * wm + 16 * mt + l7 + 8 * m8) * 144 + ks * 32 + m16 * 16);
            #pragma unroll
            for (int ntp = 0; ntp < 4; ntp++) {
                uint32_t vb[4];
                ldm_x4t(vb, vbase + (16 * ks + 8 * m8 + l7) * 528 +
                            (64 * wn + 16 * ntp + 8 * m16) * 2);
                #pragma unroll
                for (int mt = 0; mt < 2; mt++) {
                    mma_bf16(oacc[mt][2 * ntp], pa[mt], vb);
                    mma_bf16(oacc[mt][2 * ntp + 1], pa[mt], vb + 2);
                }
            }
        }
    }

    #pragma unroll
    for (int mt = 0; mt < 2; mt++)
        #pragma unroll
        for (int h = 0; h < 2; h++) {
            float v = rs[mt][h];
            v += __shfl_xor_sync(0xffffffffu, v, 1);
            v += __shfl_xor_sync(0xffffffffu, v, 2);
            if (tc == 0) {
                int row = 32 * wm + 16 * mt + 8 * h + tq;
                asm volatile("st.shared.f32 [%0], %1;" ::
                    "r"(sb + LSH_OFF + (wn * 64 + row) * 4), "f"(v) : "memory");
            }
        }
    __syncthreads();
    if (tid < 64) {
        float s = 0.f;
        #pragma unroll
        for (int w = 0; w < 4; w++) {
            float v;
            asm volatile("ld.shared.f32 %0, [%1];" : "=f"(v)
                : "r"(sb + LSH_OFF + (w * 64 + tid) * 4));
            s += v;
        }
        float riv = 1.f / s;
        asm volatile("st.shared.f32 [%0], %1;" ::
            "r"(sb + RIV_OFF + tid * 4), "f"(riv) : "memory");
    }

    #pragma unroll
    for (int mt = 0; mt < 2; mt++) {
        int row = 32 * wm + 16 * mt + tq;
        #pragma unroll
        for (int nt = 0; nt < 8; nt++) {
            int col = 64 * wn + 8 * nt + 2 * tc;
            asm volatile("st.shared.v2.f32 [%0], {%1,%2};" ::
                "r"(sb + OS_OFF + (row * 258 + col) * 4),
                "f"(oacc[mt][nt][0]), "f"(oacc[mt][nt][1]) : "memory");
            asm volatile("st.shared.v2.f32 [%0], {%1,%2};" ::
                "r"(sb + OS_OFF + ((row + 8) * 258 + col) * 4),
                "f"(oacc[mt][nt][2]), "f"(oacc[mt][nt][3]) : "memory");
        }
    }
    __syncthreads();

    const float* xb = x   + (size_t)b * NI * HW;
    float*       ob = out + (size_t)b * NI * HW;
    for (int cc = wid; cc < NI; cc += 8) {
        float ga = __ldg(gamma + cc);
        #pragma unroll
        for (int h = 0; h < 2; h++) {
            int n = lane + 32 * h;
            float riv, o;
            asm volatile("ld.shared.f32 %0, [%1];" : "=f"(riv)
                : "r"(sb + RIV_OFF + n * 4));
            asm volatile("ld.shared.f32 %0, [%1];" : "=f"(o)
                : "r"(sb + OS_OFF + (n * 258 + cc) * 4));
            size_t gi = (size_t)cc * HW + n0 + n;
            ob[gi] = ga * (o * riv) + xb[gi];
        }
    }
}

extern "C" void kernel_launch(void* const* d_in, const int* in_sizes, int n_in,
                              void* d_out, int out_size)
{
    const float* x     = (const float*)d_in[0];
    const float* wq    = (const float*)d_in[1];
    const float* bq    = (const float*)d_in[2];
    const float* wk    = (const float*)d_in[3];
    const float* bk    = (const float*)d_in[4];
    const float* wv    = (const float*)d_in[5];
    const float* bv    = (const float*)d_in[6];
    const float* gamma = (const float*)d_in[7];
    float* out = (float*)d_out;

    cudaFuncSetAttribute(proj_kernel, cudaFuncAttributeMaxDynamicSharedMemorySize, SMEM_PROJ);
    cudaFuncSetAttribute(attn_kernel, cudaFuncAttributeMaxDynamicSharedMemorySize, SMEM_ATTN);

    proj_kernel<<<dim3(16, 5, BSZ), 256, SMEM_PROJ>>>(x, wq, bq, wk, bk, wv, bv);
    attn_kernel<<<dim3(HW / MQ, BSZ), 256, SMEM_ATTN>>>(x, gamma, out);
}